// round 9
// baseline (speedup 1.0000x reference)
#include <cuda_runtime.h>
#include <stdint.h>

#define D       256
#define MITEMS  16
#define TPB     64
#define RPT     2
#define ROWS    128            // rows per block
#define CHUNK   8              // dims per pipeline stage
#define NCH     32
#define QSTR    12             // q smem row stride (words): conflict-free LDS.128
#define QBUF    (ROWS * QSTR)  // 1536 floats per buffer
#define NBUF    3
#define SM_MEM  (NBUF * QBUF)  // 4608: mem_rm offset
#define SMEM_FLOATS (SM_MEM + MITEMS * D)   // 8704 floats = 34816 B -> 6 blocks/SM
#define SMEM_BYTES  (SMEM_FLOATS * 4)
#define NEG_BIG (-1e30f)

typedef unsigned long long u64;

__device__ __forceinline__ u64 pack2(float lo, float hi) {
    u64 r; asm("mov.b64 %0, {%1, %2};" : "=l"(r) : "f"(lo), "f"(hi)); return r;
}
__device__ __forceinline__ void unpack2(u64 v, float& lo, float& hi) {
    asm("mov.b64 {%0, %1}, %2;" : "=f"(lo), "=f"(hi) : "l"(v));
}
#define FMA2(d, a, b) asm("fma.rn.f32x2 %0, %1, %2, %0;" : "+l"(d) : "l"(a), "l"(b))
#define CP16(dst, src) \
    asm volatile("cp.async.cg.shared.global [%0], [%1], 16;" :: "r"(dst), "l"(src))
#define CPCOMMIT() asm volatile("cp.async.commit_group;")
#define CPWAIT(n)  asm volatile("cp.async.wait_group %0;" :: "n"(n))

__global__ void __launch_bounds__(TPB, 6) epm_kernel(
    const float* __restrict__ q,
    const float* __restrict__ mem,
    float* __restrict__ out_ret,
    float* __restrict__ out_max,
    int nrows)
{
    extern __shared__ __align__(16) float sh[];
    float* qs     = sh;                 // 3 staging buffers
    float* mem_rm = sh + SM_MEM;        // 16 x 256 row-major (dot broadcast source)
    float* pw     = sh;                 // aliases qs buf0 after dot (words 0..512)
    int*   pidx   = (int*)(sh + ROWS * 4);   // unused by dense blend; kept for debug

    const int tid = threadIdx.x;
    const int blockRow = blockIdx.x * ROWS;
    const int nr1 = nrows - 1;
    const uint32_t qs_s = (uint32_t)__cvta_generic_to_shared(qs);

    // cp.async mapping: per chunk 128 rows x 32B = 256 CP16 = 4 per thread
    const int rsub = tid >> 1;     // 0..31
    const int sub  = tid & 1;      // 16B slot within a row's 32B chunk segment

    // ---- stage chunks 0 and 1 immediately ----
    #pragma unroll
    for (int c0 = 0; c0 < 2; c0++) {
        #pragma unroll
        for (int j = 0; j < 4; j++) {
            int rl = rsub + 32 * j;
            int rg = blockRow + rl; rg = rg < nr1 ? rg : nr1;
            const float* src = q + (size_t)rg * D + c0 * CHUNK + sub * 4;
            uint32_t dst = qs_s + (uint32_t)(c0 * QBUF + rl * QSTR + sub * 4) * 4u;
            CP16(dst, src);
        }
        CPCOMMIT();
    }

    // ---- load memory bank row-major into smem (coalesced float4 copy) ----
    {
        const float4* src4 = (const float4*)mem;
        float4* dst4 = (float4*)mem_rm;
        #pragma unroll
        for (int i = 0; i < (MITEMS * D / 4) / TPB; i++)    // 16 iters
            dst4[tid + TPB * i] = src4[tid + TPB * i];
    }

    // ---- dot mainloop: 2 rows/thread, dim-pair-packed f32x2 ----
    u64 acc[RPT][MITEMS];
    u64 ssq2[RPT];
    #pragma unroll
    for (int r = 0; r < RPT; r++) {
        ssq2[r] = 0ull;
        #pragma unroll
        for (int m = 0; m < MITEMS; m++) acc[r][m] = 0ull;
    }

    const ulonglong2* mb = (const ulonglong2*)mem_rm;   // [item][64 x 16B]

    #pragma unroll 1
    for (int ct = 0; ct < NCH; ct++) {
        // 1) my chunk-ct copies complete (keep ct+1 in flight)
        if (ct + 1 < NCH) { CPWAIT(1); } else { CPWAIT(0); }
        // 2) everyone's chunk-ct complete; all readers of buf (ct-1)%3 done
        __syncthreads();
        // 3) refill the just-freed buffer (WAR-safe per the barrier)
        if (ct + 2 < NCH) {
            #pragma unroll
            for (int j = 0; j < 4; j++) {
                int rl = rsub + 32 * j;
                int rg = blockRow + rl; rg = rg < nr1 ? rg : nr1;
                const float* src = q + (size_t)rg * D + (ct + 2) * CHUNK + sub * 4;
                uint32_t dst = qs_s +
                    (uint32_t)(((ct + 2) % NBUF) * QBUF + rl * QSTR + sub * 4) * 4u;
                CP16(dst, src);
            }
            CPCOMMIT();
        }
        // 4) compute chunk ct for rows tid, tid+64
        const float* qbuf = qs + (ct % NBUF) * QBUF;
        ulonglong2 qv[RPT], qw[RPT];
        #pragma unroll
        for (int r = 0; r < RPT; r++) {
            const float* qrow = qbuf + (tid + 64 * r) * QSTR;
            qv[r] = *(const ulonglong2*)(qrow);        // dims +0..3
            qw[r] = *(const ulonglong2*)(qrow + 4);    // dims +4..7
            FMA2(ssq2[r], qv[r].x, qv[r].x); FMA2(ssq2[r], qv[r].y, qv[r].y);
            FMA2(ssq2[r], qw[r].x, qw[r].x); FMA2(ssq2[r], qw[r].y, qw[r].y);
        }
        #pragma unroll
        for (int m = 0; m < MITEMS; m += 2) {
            ulonglong2 a0 = mb[m * 64 + ct * 2];            // mem[m][dims +0..3]
            ulonglong2 a1 = mb[m * 64 + ct * 2 + 1];        // mem[m][dims +4..7]
            ulonglong2 b0 = mb[(m + 1) * 64 + ct * 2];
            ulonglong2 b1 = mb[(m + 1) * 64 + ct * 2 + 1];
            #pragma unroll
            for (int r = 0; r < RPT; r++) {
                FMA2(acc[r][m], a0.x, qv[r].x);     FMA2(acc[r][m], a0.y, qv[r].y);
                FMA2(acc[r][m], a1.x, qw[r].x);     FMA2(acc[r][m], a1.y, qw[r].y);
                FMA2(acc[r][m + 1], b0.x, qv[r].x); FMA2(acc[r][m + 1], b0.y, qv[r].y);
                FMA2(acc[r][m + 1], b1.x, qw[r].x); FMA2(acc[r][m + 1], b1.y, qw[r].y);
            }
        }
    }
    // buf0's last reader was chunk 30 (barrier at ct=31 passed) -> pw writes safe

    // ---- epilogue per row: hsum, normalize, top-4 (first-index ties), softmax ----
    #pragma unroll
    for (int r = 0; r < RPT; r++) {
        float s[MITEMS];
        #pragma unroll
        for (int m = 0; m < MITEMS; m++) {
            float lo, hi; unpack2(acc[r][m], lo, hi);
            s[m] = lo + hi;
        }
        float sl, shi; unpack2(ssq2[r], sl, shi);
        float ssq = sl + shi;
        float inv = rsqrtf(fmaxf(ssq, 1e-24f)) * 10.0f;   // (1/|q|)/tau; mem rows unit-norm
        #pragma unroll
        for (int m = 0; m < MITEMS; m++) s[m] *= inv;

        float bw[4]; int bi[4];
        #pragma unroll
        for (int k = 0; k < 4; k++) {
            float best = NEG_BIG; int b = 0;
            #pragma unroll
            for (int m = 0; m < MITEMS; m++)
                if (s[m] > best) { best = s[m]; b = m; }   // strict > : first index wins
            bw[k] = best; bi[k] = b;
            #pragma unroll
            for (int m = 0; m < MITEMS; m++)
                s[m] = (m == b) ? NEG_BIG : s[m];
        }
        float e1 = __expf(bw[1] - bw[0]);
        float e2 = __expf(bw[2] - bw[0]);
        float e3 = __expf(bw[3] - bw[0]);
        float rden = 1.0f / (1.0f + e1 + e2 + e3);

        int rl = tid + 64 * r;
        // scatter softmax weights into a dense 16-wide row (zeros elsewhere)
        float w0 = rden, w1 = e1 * rden, w2 = e2 * rden, w3 = e3 * rden;
        float* Wr = pw + rl * 4;
        // store packed (4 weights) + indices; dense blend will expand via register select
        Wr[0] = w0; Wr[1] = w1; Wr[2] = w2; Wr[3] = w3;
        pidx[rl] = bi[0] | (bi[1] << 4) | (bi[2] << 8) | (bi[3] << 12);

        int row_g = blockRow + rl;
        if (row_g < nrows) out_max[row_g] = bw[0];
    }
    __syncthreads();

    // ---- dense blend from registers: out[r] = sum_m W[r][m] * mem[m][:] ----
    // V registers: lane owns output floats [4*lane .. +3] and [128 + 4*lane .. +3]
    const int wid  = tid >> 5;
    const int lane = tid & 31;
    const ulonglong2* mg = (const ulonglong2*)mem;    // [item][64 x 16B], L1/L2-hot

    ulonglong2 V[2 * MITEMS];
    #pragma unroll
    for (int m = 0; m < MITEMS; m++) {
        V[2 * m    ] = mg[m * (D / 4) + lane];
        V[2 * m + 1] = mg[m * (D / 4) + 32 + lane];
    }

    #pragma unroll 2
    for (int j = 0; j < ROWS / 2; j++) {              // 64 rows per warp
        int rl = wid * (ROWS / 2) + j;
        int row_g = blockRow + rl;
        float4 w4 = *(const float4*)(pw + rl * 4);    // broadcast, 1 wf
        int pk = pidx[rl];                            // broadcast
        // expand sparse weights into dense 16-vector in registers
        float wv[MITEMS];
        #pragma unroll
        for (int m = 0; m < MITEMS; m++) wv[m] = 0.0f;
        wv[(pk      ) & 15] = w4.x;
        wv[(pk >> 4 ) & 15] = w4.y;
        wv[(pk >> 8 ) & 15] = w4.z;
        wv[(pk >> 12) & 15] = w4.w;

        u64 o0 = 0ull, o1 = 0ull, o2 = 0ull, o3 = 0ull;
        #pragma unroll
        for (int m = 0; m < MITEMS; m++) {
            u64 wm = pack2(wv[m], wv[m]);
            FMA2(o0, V[2 * m    ].x, wm);
            FMA2(o1, V[2 * m    ].y, wm);
            FMA2(o2, V[2 * m + 1].x, wm);
            FMA2(o3, V[2 * m + 1].y, wm);
        }
        if (row_g < nrows) {
            ulonglong2* op = (ulonglong2*)(out_ret + (size_t)row_g * D);
            ulonglong2 v0; v0.x = o0; v0.y = o1;
            ulonglong2 v1; v1.x = o2; v1.y = o3;
            op[lane]      = v0;
            op[32 + lane] = v1;
        }
    }
}

extern "C" void kernel_launch(void* const* d_in, const int* in_sizes, int n_in,
                              void* d_out, int out_size)
{
    const float* q   = (const float*)d_in[0];
    const float* mem = (const float*)d_in[1];
    int nrows = in_sizes[0] / D;              // 131072
    float* out_ret = (float*)d_out;
    float* out_max = out_ret + (size_t)nrows * D;

    cudaFuncSetAttribute(epm_kernel,
                         cudaFuncAttributeMaxDynamicSharedMemorySize, SMEM_BYTES);

    int grid = (nrows + ROWS - 1) / ROWS;     // 1024
    epm_kernel<<<grid, TPB, SMEM_BYTES>>>(q, mem, out_ret, out_max, nrows);
}

// round 10
// speedup vs baseline: 2.3204x; 2.3204x over previous
#include <cuda_runtime.h>
#include <stdint.h>

#define D        256
#define MITEMS   16
#define TPB      256
#define NWARP    8
#define GRID     148
#define RPW      111           // rows per warp (148*8*111 >= 131072)
#define TILE     64            // rows per warp-tile
#define CHUNK    16            // dims per pipeline chunk (64 B per row)
#define NCH      16            // D / CHUNK
#define NBUF     4
#define QSTR     20            // staging row stride (floats): LDS.128 conflict-free
#define BUFW     (TILE * QSTR) // 1280 floats per buffer
#define RINGW    (NBUF * BUFW) // 5120 floats per warp ring
#define SM_MEM   (NWARP * RINGW)           // 40960: mem_rm offset
#define SM_PW    (SM_MEM + MITEMS * D)     // 45056: pw offset
#define PWSTR    8                          // per-row pw stride (4 w + idx + pad)
#define SMEM_FLOATS (SM_PW + NWARP * TILE * PWSTR)   // 49152 floats = 196608 B
#define SMEM_BYTES  (SMEM_FLOATS * 4)
#define NEG_BIG (-1e30f)

typedef unsigned long long u64;

__device__ __forceinline__ u64 pack2(float lo, float hi) {
    u64 r; asm("mov.b64 %0, {%1, %2};" : "=l"(r) : "f"(lo), "f"(hi)); return r;
}
__device__ __forceinline__ void unpack2(u64 v, float& lo, float& hi) {
    asm("mov.b64 {%0, %1}, %2;" : "=f"(lo), "=f"(hi) : "l"(v));
}
#define FMA2(d, a, b) asm("fma.rn.f32x2 %0, %1, %2, %0;" : "+l"(d) : "l"(a), "l"(b))
#define CP16(dst, src) \
    asm volatile("cp.async.cg.shared.global [%0], [%1], 16;" :: "r"(dst), "l"(src))
#define CPCOMMIT() asm volatile("cp.async.commit_group;")
#define CPWAIT(n)  asm volatile("cp.async.wait_group %0;" :: "n"(n))

__global__ void __launch_bounds__(TPB, 1) epm_kernel(
    const float* __restrict__ q,
    const float* __restrict__ mem,
    float* __restrict__ out_ret,
    float* __restrict__ out_max,
    int nrows)
{
    extern __shared__ __align__(16) float sh[];
    const int tid  = threadIdx.x;
    const int wid  = tid >> 5;
    const int lane = tid & 31;

    float* ring   = sh + wid * RINGW;
    float* mem_rm = sh + SM_MEM;
    float* pw     = sh + SM_PW + wid * TILE * PWSTR;
    const uint32_t ring_s = (uint32_t)__cvta_generic_to_shared(ring);

    // ---- block-cooperative: memory bank row-major into smem ----
    {
        const float4* s4 = (const float4*)mem;
        float4* d4 = (float4*)mem_rm;
        #pragma unroll
        for (int i = 0; i < (MITEMS * D / 4) / TPB; i++)   // 4 iters
            d4[tid + TPB * i] = s4[tid + TPB * i];
    }
    __syncthreads();    // the ONLY block barrier

    // ---- warp work assignment ----
    const int wg    = blockIdx.x * NWARP + wid;
    const int base  = wg * RPW;
    int count = nrows - base;
    if (count > RPW) count = RPW;

    // cp.async lane mapping within a 64-row tile chunk:
    const int rsub = lane >> 2;    // 0..7 (rows rsub + 8j)
    const int sub  = lane & 3;     // 16B slot within the 64B row segment

    if (count > 0) {
        for (int tb = 0; tb < count; tb += TILE) {
            const int tr    = min(TILE, count - tb);
            const int rowg0 = base + tb;

            // ---- prologue: issue chunks 0..2 into bufs 0..2 ----
            #pragma unroll
            for (int c0 = 0; c0 < 3; c0++) {
                #pragma unroll
                for (int j = 0; j < 8; j++) {
                    int rl = rsub + 8 * j;
                    if (rl < tr) {
                        const float* src = q + (size_t)(rowg0 + rl) * D + c0 * CHUNK + sub * 4;
                        uint32_t dst = ring_s +
                            (uint32_t)(c0 * BUFW + rl * QSTR + sub * 4) * 4u;
                        CP16(dst, src);
                    }
                }
                CPCOMMIT();
            }

            // ---- dot mainloop: warp-private ring, no block barriers ----
            u64 accA[MITEMS], accB[MITEMS], ssqA = 0ull, ssqB = 0ull;
            #pragma unroll
            for (int m = 0; m < MITEMS; m++) { accA[m] = 0ull; accB[m] = 0ull; }

            #pragma unroll 1
            for (int ct = 0; ct < NCH; ct++) {
                if (ct <= NCH - 3)      { CPWAIT(2); }
                else if (ct == NCH - 2) { CPWAIT(1); }
                else                    { CPWAIT(0); }
                __syncwarp();

                // refill the just-freed buffer (this warp finished reading it)
                if (ct + 3 < NCH) {
                    #pragma unroll
                    for (int j = 0; j < 8; j++) {
                        int rl = rsub + 8 * j;
                        if (rl < tr) {
                            const float* src = q + (size_t)(rowg0 + rl) * D
                                             + (ct + 3) * CHUNK + sub * 4;
                            uint32_t dst = ring_s +
                                (uint32_t)(((ct + 3) & 3) * BUFW + rl * QSTR + sub * 4) * 4u;
                            CP16(dst, src);
                        }
                    }
                    CPCOMMIT();
                }

                const float* qb = ring + (ct & 3) * BUFW;
                ulonglong2 qA[4], qB[4];
                #pragma unroll
                for (int g = 0; g < 4; g++) {
                    qA[g] = *(const ulonglong2*)(qb + lane * QSTR + 4 * g);
                    qB[g] = *(const ulonglong2*)(qb + (lane + 32) * QSTR + 4 * g);
                    FMA2(ssqA, qA[g].x, qA[g].x); FMA2(ssqA, qA[g].y, qA[g].y);
                    FMA2(ssqB, qB[g].x, qB[g].x); FMA2(ssqB, qB[g].y, qB[g].y);
                }
                #pragma unroll
                for (int m = 0; m < MITEMS; m++) {
                    const ulonglong2* mt = (const ulonglong2*)(mem_rm + m * D + ct * CHUNK);
                    ulonglong2 v0 = mt[0], v1 = mt[1], v2 = mt[2], v3 = mt[3]; // broadcast
                    FMA2(accA[m], v0.x, qA[0].x); FMA2(accA[m], v0.y, qA[0].y);
                    FMA2(accA[m], v1.x, qA[1].x); FMA2(accA[m], v1.y, qA[1].y);
                    FMA2(accA[m], v2.x, qA[2].x); FMA2(accA[m], v2.y, qA[2].y);
                    FMA2(accA[m], v3.x, qA[3].x); FMA2(accA[m], v3.y, qA[3].y);
                    FMA2(accB[m], v0.x, qB[0].x); FMA2(accB[m], v0.y, qB[0].y);
                    FMA2(accB[m], v1.x, qB[1].x); FMA2(accB[m], v1.y, qB[1].y);
                    FMA2(accB[m], v2.x, qB[2].x); FMA2(accB[m], v2.y, qB[2].y);
                    FMA2(accB[m], v3.x, qB[3].x); FMA2(accB[m], v3.y, qB[3].y);
                }
            }

            // ---- epilogue: 2 rows per lane -> pw (stride 8) + out_max ----
            #pragma unroll
            for (int r = 0; r < 2; r++) {
                int rl = lane + 32 * r;
                float s[MITEMS];
                #pragma unroll
                for (int m = 0; m < MITEMS; m++) {
                    float lo, hi; unpack2(r == 0 ? accA[m] : accB[m], lo, hi);
                    s[m] = lo + hi;
                }
                float sl, shi; unpack2(r == 0 ? ssqA : ssqB, sl, shi);
                float inv = rsqrtf(fmaxf(sl + shi, 1e-24f)) * 10.0f; // (1/|q|)/tau
                #pragma unroll
                for (int m = 0; m < MITEMS; m++) s[m] *= inv;

                float bw[4]; int bi[4];
                #pragma unroll
                for (int k = 0; k < 4; k++) {
                    float best = NEG_BIG; int b = 0;
                    #pragma unroll
                    for (int m = 0; m < MITEMS; m++)
                        if (s[m] > best) { best = s[m]; b = m; }  // first-index ties
                    bw[k] = best; bi[k] = b;
                    #pragma unroll
                    for (int m = 0; m < MITEMS; m++)
                        s[m] = (m == b) ? NEG_BIG : s[m];
                }
                float e1 = __expf(bw[1] - bw[0]);
                float e2 = __expf(bw[2] - bw[0]);
                float e3 = __expf(bw[3] - bw[0]);
                float rden = 1.0f / (1.0f + e1 + e2 + e3);

                if (rl < tr) {
                    float* Wr = pw + rl * PWSTR;
                    Wr[0] = rden;
                    Wr[1] = e1 * rden;
                    Wr[2] = e2 * rden;
                    Wr[3] = e3 * rden;
                    ((int*)Wr)[4] = bi[0] | (bi[1] << 4) | (bi[2] << 8) | (bi[3] << 12);
                    out_max[rowg0 + rl] = bw[0];
                }
            }
            __syncwarp();

            // ---- sparse blend: warp-per-row gathers from mem_rm ----
            #pragma unroll 2
            for (int j = 0; j < TILE; j++) {
                if (j >= tr) break;
                const float* Wr = pw + j * PWSTR;
                float4 w4 = *(const float4*)Wr;         // broadcast
                int pk = ((const int*)Wr)[4];
                u64 W0 = pack2(w4.x, w4.x), W1 = pack2(w4.y, w4.y);
                u64 W2 = pack2(w4.z, w4.z), W3 = pack2(w4.w, w4.w);
                const ulonglong2* r0 = (const ulonglong2*)(mem_rm + ((pk      ) & 15) * D);
                const ulonglong2* r1 = (const ulonglong2*)(mem_rm + ((pk >> 4 ) & 15) * D);
                const ulonglong2* r2 = (const ulonglong2*)(mem_rm + ((pk >> 8 ) & 15) * D);
                const ulonglong2* r3 = (const ulonglong2*)(mem_rm + ((pk >> 12) & 15) * D);

                u64 o0 = 0ull, o1 = 0ull, o2 = 0ull, o3 = 0ull;
                ulonglong2 a;
                a = r0[lane];      FMA2(o0, a.x, W0); FMA2(o1, a.y, W0);
                a = r1[lane];      FMA2(o0, a.x, W1); FMA2(o1, a.y, W1);
                a = r2[lane];      FMA2(o0, a.x, W2); FMA2(o1, a.y, W2);
                a = r3[lane];      FMA2(o0, a.x, W3); FMA2(o1, a.y, W3);
                a = r0[32 + lane]; FMA2(o2, a.x, W0); FMA2(o3, a.y, W0);
                a = r1[32 + lane]; FMA2(o2, a.x, W1); FMA2(o3, a.y, W1);
                a = r2[32 + lane]; FMA2(o2, a.x, W2); FMA2(o3, a.y, W2);
                a = r3[32 + lane]; FMA2(o2, a.x, W3); FMA2(o3, a.y, W3);

                ulonglong2* op = (ulonglong2*)(out_ret + (size_t)(rowg0 + j) * D);
                ulonglong2 v0; v0.x = o0; v0.y = o1;
                ulonglong2 v1; v1.x = o2; v1.y = o3;
                op[lane]      = v0;
                op[32 + lane] = v1;
            }
            __syncwarp();
        }
    }
}

extern "C" void kernel_launch(void* const* d_in, const int* in_sizes, int n_in,
                              void* d_out, int out_size)
{
    const float* q   = (const float*)d_in[0];
    const float* mem = (const float*)d_in[1];
    int nrows = in_sizes[0] / D;              // 131072
    float* out_ret = (float*)d_out;
    float* out_max = out_ret + (size_t)nrows * D;

    cudaFuncSetAttribute(epm_kernel,
                         cudaFuncAttributeMaxDynamicSharedMemorySize, SMEM_BYTES);

    epm_kernel<<<GRID, TPB, SMEM_BYTES>>>(q, mem, out_ret, out_max, nrows);
}